// round 6
// baseline (speedup 1.0000x reference)
#include <cuda_runtime.h>
#include <math.h>

#define ALPHA 0.2f
typedef unsigned long long ull;
constexpr int Bc = 8;
constexpr int Nc = 2048;
constexpr int Cc = 128;
constexpr int NCH = 128;           // chunks per batch
constexpr int CHK = 16;            // rows per chunk

// ---------------- device scratch ----------------
__device__ __align__(16) float g_h[Bc * Nc * Cc];
__device__ float g_s1[Bc * Nc];
__device__ float g_s2[Bc * Nc];
__device__ __align__(16) float g_w12[2 * Cc];         // w1 = W@a1, w2 = W@a2
__device__ float g_v[Bc * Nc];
__device__ int   g_perm[Bc * Nc];
__device__ float g_Ae[Bc * Nc];
__device__ float g_Ee[Bc * Nc];
__device__ float g_AS[Bc * (Nc + 1)];
__device__ float g_ES[Bc * (Nc + 1)];
__device__ __align__(16) float g_FWD[Bc * Nc * Cc];
__device__ __align__(16) float g_BWD[Bc * Nc * Cc];
__device__ __align__(16) float g_TF[Bc * NCH * Cc];
__device__ __align__(16) float g_TB[Bc * NCH * Cc];

// ---------------- Kernel 0 (side stream): w1 = W@a1, w2 = W@a2 -----------
__global__ __launch_bounds__(128)
void wvec_kernel(const float* __restrict__ W, const float* __restrict__ a) {
    const int c = threadIdx.x;
    const float4* Wr = (const float4*)&W[c * 128];
    float p1 = 0.f, p2 = 0.f;
#pragma unroll 8
    for (int q = 0; q < 32; q++) {
        float4 wv = __ldg(&Wr[q]);
        float4 a1 = __ldg(&((const float4*)a)[q]);
        float4 a2 = __ldg(&((const float4*)a)[32 + q]);
        p1 += wv.x * a1.x + wv.y * a1.y + wv.z * a1.z + wv.w * a1.w;
        p2 += wv.x * a2.x + wv.y * a2.y + wv.z * a2.z + wv.w * a2.w;
    }
    g_w12[c] = p1;
    g_w12[128 + c] = p2;
}

// ---------------- Kernel 0b (side stream): s1/s2 from text ---------------
__global__ __launch_bounds__(256)
void s12_kernel(const float* __restrict__ X) {
    int row = blockIdx.x * 8 + (threadIdx.x >> 5);
    int lane = threadIdx.x & 31;
    float4 hv = __ldg(&((const float4*)X)[(row << 5) + lane]);
    float4 a1 = ((const float4*)g_w12)[lane];
    float4 a2 = ((const float4*)g_w12)[32 + lane];
    float p1 = hv.x * a1.x + hv.y * a1.y + hv.z * a1.z + hv.w * a1.w;
    float p2 = hv.x * a2.x + hv.y * a2.y + hv.z * a2.z + hv.w * a2.w;
#pragma unroll
    for (int o = 16; o; o >>= 1) {
        p1 += __shfl_down_sync(0xffffffffu, p1, o);
        p2 += __shfl_down_sync(0xffffffffu, p2, o);
    }
    if (lane == 0) { g_s1[row] = p1; g_s2[row] = p2; }
}

// ---------------- Kernel 1 (main stream): h = text @ W, BM=64 ------------
__global__ __launch_bounds__(256)
void gemm_kernel(const float* __restrict__ X, const float* __restrict__ W) {
    __shared__ float As[16][64];
    __shared__ float Bs[16][128];
    const int tid = threadIdx.x;
    const int tx = tid & 15;
    const int ty = tid >> 4;
    const int m0 = blockIdx.x * 64;

    float acc[4][8];
#pragma unroll
    for (int i = 0; i < 4; i++)
#pragma unroll
        for (int j = 0; j < 8; j++) acc[i][j] = 0.f;

    for (int k0 = 0; k0 < 128; k0 += 16) {
        {
            int m = tid >> 2;
            int kq = (tid & 3) * 4;
            float4 t = *(const float4*)&X[(m0 + m) * 128 + k0 + kq];
            As[kq + 0][m] = t.x; As[kq + 1][m] = t.y;
            As[kq + 2][m] = t.z; As[kq + 3][m] = t.w;
        }
#pragma unroll
        for (int l = 0; l < 2; l++) {
            int fid = tid + l * 256;
            int kk = fid >> 5;
            int nq = (fid & 31) * 4;
            *(float4*)&Bs[kk][nq] = *(const float4*)&W[(k0 + kk) * 128 + nq];
        }
        __syncthreads();
#pragma unroll
        for (int k = 0; k < 16; k++) {
            float av[4], bv[8];
            *(float4*)&av[0] = *(float4*)&As[k][ty * 4];
            *(float4*)&bv[0] = *(float4*)&Bs[k][tx * 8];
            *(float4*)&bv[4] = *(float4*)&Bs[k][tx * 8 + 4];
#pragma unroll
            for (int i = 0; i < 4; i++)
#pragma unroll
                for (int j = 0; j < 8; j++) acc[i][j] += av[i] * bv[j];
        }
        __syncthreads();
    }
#pragma unroll
    for (int i = 0; i < 4; i++) {
        int m = m0 + ty * 4 + i;
#pragma unroll
        for (int j = 0; j < 8; j += 4) {
            *(float4*)&g_h[m * 128 + tx * 8 + j] =
                make_float4(acc[i][j], acc[i][j + 1], acc[i][j + 2], acc[i][j + 3]);
        }
    }
}

// float <-> order-preserving uint32
__device__ __forceinline__ unsigned f2o(float x) {
    unsigned u = __float_as_uint(x);
    return u ^ ((u >> 31) ? 0xFFFFFFFFu : 0x80000000u);
}
__device__ __forceinline__ float o2f(unsigned u) {
    u ^= (u & 0x80000000u) ? 0x80000000u : 0xFFFFFFFFu;
    return __uint_as_float(u);
}

__device__ __forceinline__ float warp_incl_scan(float x, int lane) {
#pragma unroll
    for (int o = 1; o < 32; o <<= 1) {
        float y = __shfl_up_sync(0xffffffffu, x, o);
        if (lane >= o) x += y;
    }
    return x;
}

__device__ __forceinline__ float block_excl_pairsum(float ps, int lane, int wid,
                                                    float* wred) {
    float w = warp_incl_scan(ps, lane);
    if (lane == 31) wred[wid] = w;
    __syncthreads();
    if (wid == 0) {
        float s = wred[lane];
        s = warp_incl_scan(s, lane);
        wred[lane] = s;
    }
    __syncthreads();
    float base = (wid > 0) ? wred[wid - 1] : 0.f;
    return base + (w - ps);
}

// ---------------- Kernel 3 (side stream): bitonic sort + scalar scans ----
__global__ __launch_bounds__(1024)
void sort_kernel() {
    __shared__ ull sk[2048];
    __shared__ float wred[32];
    __shared__ float sh_vmax;
    const int b = blockIdx.x, t = threadIdx.x;
    const int lane = t & 31, wid = t >> 5;

    ull e0 = ((ull)f2o(g_s2[b * 2048 + 2 * t]) << 32) | (unsigned)(2 * t);
    ull e1 = ((ull)f2o(g_s2[b * 2048 + 2 * t + 1]) << 32) | (unsigned)(2 * t + 1);

    for (int k = 2; k <= 2048; k <<= 1) {
        const bool asc = ((2 * t) & k) == 0;
        int j = k >> 1;
        for (; j >= 64; j >>= 1) {
            sk[2 * t] = e0; sk[2 * t + 1] = e1;
            __syncthreads();
            int m = j >> 1, p = t ^ m;
            ull f0 = sk[2 * p], f1 = sk[2 * p + 1];
            __syncthreads();
            bool keepmin = (((t & m) == 0) == asc);
            e0 = keepmin ? (e0 < f0 ? e0 : f0) : (e0 > f0 ? e0 : f0);
            e1 = keepmin ? (e1 < f1 ? e1 : f1) : (e1 > f1 ? e1 : f1);
        }
        for (; j >= 2; j >>= 1) {
            int m = j >> 1;
            ull f0 = __shfl_xor_sync(0xffffffffu, e0, m);
            ull f1 = __shfl_xor_sync(0xffffffffu, e1, m);
            bool keepmin = (((lane & m) == 0) == asc);
            e0 = keepmin ? (e0 < f0 ? e0 : f0) : (e0 > f0 ? e0 : f0);
            e1 = keepmin ? (e1 < f1 ? e1 : f1) : (e1 > f1 ? e1 : f1);
        }
        if ((e0 > e1) == asc) { ull tmp = e0; e0 = e1; e1 = tmp; }
    }

    float v0 = o2f((unsigned)(e0 >> 32));
    float v1 = o2f((unsigned)(e1 >> 32));
    g_v[b * 2048 + 2 * t]     = v0;
    g_v[b * 2048 + 2 * t + 1] = v1;
    g_perm[b * 2048 + 2 * t]     = (int)(unsigned)e0;
    g_perm[b * 2048 + 2 * t + 1] = (int)(unsigned)e1;
    if (t == 1023) sh_vmax = v1;
    __syncthreads();
    const float vmax = sh_vmax;

    float av0 = expf(ALPHA * v0), av1 = expf(ALPHA * v1);
    g_Ae[b * 2048 + 2 * t]     = av0;
    g_Ae[b * 2048 + 2 * t + 1] = av1;
    float exA = block_excl_pairsum(av0 + av1, lane, wid, wred);
    g_AS[b * 2049 + 2 * t + 1] = exA + av0;
    g_AS[b * 2049 + 2 * t + 2] = exA + av0 + av1;
    if (t == 0) g_AS[b * 2049] = 0.f;

    float ev0 = expf(v0 - vmax), ev1 = expf(v1 - vmax);
    g_Ee[b * 2048 + 2 * t]     = ev0;
    g_Ee[b * 2048 + 2 * t + 1] = ev1;
    float* sx = (float*)sk;
    __syncthreads();
    sx[2 * t] = ev0; sx[2 * t + 1] = ev1;
    __syncthreads();
    float r0 = sx[2047 - 2 * t];
    float r1 = sx[2046 - 2 * t];
    __syncthreads();
    float exE = block_excl_pairsum(r0 + r1, lane, wid, wred);
    g_ES[b * 2049 + 2047 - 2 * t] = exE + r0;
    g_ES[b * 2049 + 2046 - 2 * t] = exE + r0 + r1;
    if (t == 0) g_ES[b * 2049 + 2048] = 0.f;
}

// ---------------- Kernel 4: chunked vector scans (batched gathers) -------
__global__ __launch_bounds__(64)
void scanA_kernel() {
    const int b = blockIdx.x >> 7;
    const int c = blockIdx.x & 127;
    const int dir = threadIdx.x >> 5;
    const int lane = threadIdx.x & 31;
    const int kb = b * 2048 + c * CHK;
    const float4* h4 = (const float4*)g_h;

    int src[CHK]; float w[CHK];
    const float* wsrc = dir ? g_Ee : g_Ae;
#pragma unroll
    for (int r = 0; r < CHK; r++) {
        src[r] = __ldg(&g_perm[kb + r]);
        w[r]   = __ldg(&wsrc[kb + r]);
    }
    float4 hv[CHK];
#pragma unroll
    for (int r = 0; r < CHK; r++)
        hv[r] = __ldg(&h4[((b * 2048 + src[r]) << 5) + lane]);

    float4 run = make_float4(0.f, 0.f, 0.f, 0.f);
    if (dir == 0) {
        float4* o4 = (float4*)g_FWD;
#pragma unroll
        for (int r = 0; r < CHK; r++) {
            run.x += w[r] * hv[r].x; run.y += w[r] * hv[r].y;
            run.z += w[r] * hv[r].z; run.w += w[r] * hv[r].w;
            o4[((kb + r) << 5) + lane] = run;
        }
        ((float4*)g_TF)[((b * NCH + c) << 5) + lane] = run;
    } else {
        float4* o4 = (float4*)g_BWD;
#pragma unroll
        for (int r = CHK - 1; r >= 0; r--) {
            run.x += w[r] * hv[r].x; run.y += w[r] * hv[r].y;
            run.z += w[r] * hv[r].z; run.w += w[r] * hv[r].w;
            o4[((kb + r) << 5) + lane] = run;
        }
        ((float4*)g_TB)[((b * NCH + c) << 5) + lane] = run;
    }
}

// ---------------- Kernel 5: chunk totals -> exclusive offsets (parallel) -
// grid = B*2, block = 1024: warp w = float4 channel lane, lane = 4-chunk group
__global__ __launch_bounds__(1024)
void scanB_kernel() {
    const int b = blockIdx.x >> 1;
    const int dir = blockIdx.x & 1;
    const int w = threadIdx.x >> 5;      // float4 channel 0..31
    const int lane = threadIdx.x & 31;   // chunk group 0..31 (4 chunks each)
    float4* T4 = dir ? (float4*)g_TB : (float4*)g_TF;

    float4 v[4]; int cc[4];
#pragma unroll
    for (int i = 0; i < 4; i++) {
        int o = lane * 4 + i;                 // scan order index
        cc[i] = dir ? (NCH - 1 - o) : o;      // actual chunk
        v[i] = T4[((b * NCH + cc[i]) << 5) + w];
    }
    float4 tot;
    tot.x = v[0].x + v[1].x + v[2].x + v[3].x;
    tot.y = v[0].y + v[1].y + v[2].y + v[3].y;
    tot.z = v[0].z + v[1].z + v[2].z + v[3].z;
    tot.w = v[0].w + v[1].w + v[2].w + v[3].w;
    // exclusive warp scan per component
    float4 run;
    run.x = warp_incl_scan(tot.x, lane) - tot.x;
    run.y = warp_incl_scan(tot.y, lane) - tot.y;
    run.z = warp_incl_scan(tot.z, lane) - tot.z;
    run.w = warp_incl_scan(tot.w, lane) - tot.w;
#pragma unroll
    for (int i = 0; i < 4; i++) {
        T4[((b * NCH + cc[i]) << 5) + w] = run;
        run.x += v[i].x; run.y += v[i].y; run.z += v[i].z; run.w += v[i].w;
    }
}

// ---------------- Kernel 6: output -----------------------------------
__global__ __launch_bounds__(256)
void out_kernel(float* __restrict__ out) {
    __shared__ float sh_c1[8], sh_c2[8];
    __shared__ int   sh_k[8];
    const int lane = threadIdx.x & 31;
    const int rr = threadIdx.x >> 5;
    const int row = blockIdx.x * 8 + rr;
    const int b = row >> 11;

    if (lane == 0) {
        float s1 = __ldg(&g_s1[row]);
        const float* v = &g_v[b * 2048];
        float vmax = __ldg(&v[2047]);
        float T = -s1;
        int lo = 0, hi = 2048;
        while (lo < hi) {
            int mid = (lo + hi) >> 1;
            if (__ldg(&v[mid]) <= T) lo = mid + 1; else hi = mid;
        }
        int k = lo;
        float z = s1 + vmax;
        float m = z > 0.f ? z : ALPHA * z;
        float c1 = expf(z - m);
        float c2 = expf(ALPHA * s1 - m);
        float den = c1 * __ldg(&g_ES[b * 2049 + k]) + c2 * __ldg(&g_AS[b * 2049 + k]);
        float inv = 1.f / den;
        sh_k[rr] = k;
        sh_c1[rr] = c1 * inv;
        sh_c2[rr] = c2 * inv;
    }
    __syncthreads();

    const int k = sh_k[rr];
    const float c1 = sh_c1[rr], c2 = sh_c2[rr];
    float4 suf = make_float4(0.f, 0.f, 0.f, 0.f);
    float4 pre = make_float4(0.f, 0.f, 0.f, 0.f);
    if (k < 2048) {
        float4 s0 = __ldg(&((const float4*)g_BWD)[((b * 2048 + k) << 5) + lane]);
        float4 t0 = __ldg(&((const float4*)g_TB)[((b * NCH + (k >> 4)) << 5) + lane]);
        suf.x = s0.x + t0.x; suf.y = s0.y + t0.y;
        suf.z = s0.z + t0.z; suf.w = s0.w + t0.w;
    }
    if (k > 0) {
        float4 s0 = __ldg(&((const float4*)g_FWD)[((b * 2048 + k - 1) << 5) + lane]);
        float4 t0 = __ldg(&((const float4*)g_TF)[((b * NCH + ((k - 1) >> 4)) << 5) + lane]);
        pre.x = s0.x + t0.x; pre.y = s0.y + t0.y;
        pre.z = s0.z + t0.z; pre.w = s0.w + t0.w;
    }
    float4 hv = __ldg(&((const float4*)g_h)[(row << 5) + lane]);
    float4 o;
    o.x = c1 * suf.x + c2 * pre.x + ALPHA * hv.x;
    o.y = c1 * suf.y + c2 * pre.y + ALPHA * hv.y;
    o.z = c1 * suf.z + c2 * pre.z + ALPHA * hv.z;
    o.w = c1 * suf.w + c2 * pre.w + ALPHA * hv.w;
    o.x = o.x > 0.f ? o.x : (expf(o.x) - 1.f);
    o.y = o.y > 0.f ? o.y : (expf(o.y) - 1.f);
    o.z = o.z > 0.f ? o.z : (expf(o.z) - 1.f);
    o.w = o.w > 0.f ? o.w : (expf(o.w) - 1.f);
    ((float4*)out)[(row << 5) + lane] = o;
}

// ---------------- launcher: fork side stream for s12 + sort ----------
static cudaStream_t g_side = nullptr;
static cudaEvent_t g_ev_fork, g_ev_join;

extern "C" void kernel_launch(void* const* d_in, const int* in_sizes, int n_in,
                              void* d_out, int out_size) {
    const float* text = nullptr;
    const float* W = nullptr;
    const float* a = nullptr;
    for (int i = 0; i < n_in; i++) {
        if (in_sizes[i] == Bc * Nc * Cc)      text = (const float*)d_in[i];
        else if (in_sizes[i] == Cc * Cc)      W    = (const float*)d_in[i];
        else if (in_sizes[i] == 2 * Cc)       a    = (const float*)d_in[i];
    }
    float* out = (float*)d_out;

    if (!g_side) {
        cudaStreamCreateWithFlags(&g_side, cudaStreamNonBlocking);
        cudaEventCreateWithFlags(&g_ev_fork, cudaEventDisableTiming);
        cudaEventCreateWithFlags(&g_ev_join, cudaEventDisableTiming);
    }

    // fork: side stream computes w12 -> s1/s2 -> sort (independent of h)
    cudaEventRecord(g_ev_fork, 0);
    cudaStreamWaitEvent(g_side, g_ev_fork, 0);
    wvec_kernel<<<1, 128, 0, g_side>>>(W, a);
    s12_kernel<<<(Bc * Nc) / 8, 256, 0, g_side>>>(text);
    sort_kernel<<<Bc, 1024, 0, g_side>>>();
    cudaEventRecord(g_ev_join, g_side);

    // main stream: h = text @ W runs concurrently with the side chain
    gemm_kernel<<<(Bc * Nc) / 64, 256>>>(text, W);

    // join, then the dependent tail
    cudaStreamWaitEvent(0, g_ev_join, 0);
    scanA_kernel<<<Bc * NCH, 64>>>();
    scanB_kernel<<<Bc * 2, 1024>>>();
    out_kernel<<<(Bc * Nc) / 8, 256>>>(out);
}

// round 10
// speedup vs baseline: 1.9564x; 1.9564x over previous
#include <cuda_runtime.h>
#include <math.h>

#define ALPHA 0.2f
typedef unsigned long long ull;
constexpr int Bc = 8;
constexpr int Nc = 2048;
constexpr int Cc = 128;
constexpr int NCH = 128;           // chunks per batch
constexpr int CHK = 16;            // rows per chunk

// ---------------- device scratch ----------------
__device__ __align__(16) float g_h[Bc * Nc * Cc];
__device__ float g_s1[Bc * Nc];
__device__ float g_s2[Bc * Nc];
__device__ __align__(16) float g_w12[2 * Cc];         // w1 = W@a1, w2 = W@a2
__device__ float g_v[Bc * Nc];
__device__ int   g_perm[Bc * Nc];
__device__ float g_Ae[Bc * Nc];
__device__ float g_Ee[Bc * Nc];
__device__ float g_AS[Bc * (Nc + 1)];
__device__ float g_ES[Bc * (Nc + 1)];
__device__ __align__(16) float g_FWD[Bc * Nc * Cc];
__device__ __align__(16) float g_BWD[Bc * Nc * Cc];
__device__ __align__(16) float g_TF[Bc * NCH * Cc];
__device__ __align__(16) float g_TB[Bc * NCH * Cc];

// ---------------- Kernel 0 (side stream): w1 = W@a1, w2 = W@a2 -----------
__global__ __launch_bounds__(128)
void wvec_kernel(const float* __restrict__ W, const float* __restrict__ a) {
    const int c = threadIdx.x;
    const float4* Wr = (const float4*)&W[c * 128];
    float p1 = 0.f, p2 = 0.f;
#pragma unroll 8
    for (int q = 0; q < 32; q++) {
        float4 wv = __ldg(&Wr[q]);
        float4 a1 = __ldg(&((const float4*)a)[q]);
        float4 a2 = __ldg(&((const float4*)a)[32 + q]);
        p1 += wv.x * a1.x + wv.y * a1.y + wv.z * a1.z + wv.w * a1.w;
        p2 += wv.x * a2.x + wv.y * a2.y + wv.z * a2.z + wv.w * a2.w;
    }
    g_w12[c] = p1;
    g_w12[128 + c] = p2;
}

// ---------------- Kernel 0b (side stream): s1/s2 from text ---------------
__global__ __launch_bounds__(256)
void s12_kernel(const float* __restrict__ X) {
    int row = blockIdx.x * 8 + (threadIdx.x >> 5);
    int lane = threadIdx.x & 31;
    float4 hv = __ldg(&((const float4*)X)[(row << 5) + lane]);
    float4 a1 = ((const float4*)g_w12)[lane];
    float4 a2 = ((const float4*)g_w12)[32 + lane];
    float p1 = hv.x * a1.x + hv.y * a1.y + hv.z * a1.z + hv.w * a1.w;
    float p2 = hv.x * a2.x + hv.y * a2.y + hv.z * a2.z + hv.w * a2.w;
#pragma unroll
    for (int o = 16; o; o >>= 1) {
        p1 += __shfl_down_sync(0xffffffffu, p1, o);
        p2 += __shfl_down_sync(0xffffffffu, p2, o);
    }
    if (lane == 0) { g_s1[row] = p1; g_s2[row] = p2; }
}

// ---------------- Kernel 1 (main stream): h = text @ W, BM=128 -----------
__global__ __launch_bounds__(256, 1)
void gemm_kernel(const float* __restrict__ X, const float* __restrict__ W) {
    __shared__ float As[16][128];   // [k][m]
    __shared__ float Bs[16][128];   // [k][n]
    const int tid = threadIdx.x;
    const int tx = tid & 15;
    const int ty = tid >> 4;
    const int m0 = blockIdx.x * 128;

    float acc[8][8];
#pragma unroll
    for (int i = 0; i < 8; i++)
#pragma unroll
        for (int j = 0; j < 8; j++) acc[i][j] = 0.f;

    for (int k0 = 0; k0 < 128; k0 += 16) {
#pragma unroll
        for (int l = 0; l < 2; l++) {
            int fid = tid + l * 256;
            int m = fid >> 2;
            int kq = (fid & 3) * 4;
            float4 t = *(const float4*)&X[(m0 + m) * 128 + k0 + kq];
            As[kq + 0][m] = t.x; As[kq + 1][m] = t.y;
            As[kq + 2][m] = t.z; As[kq + 3][m] = t.w;
        }
#pragma unroll
        for (int l = 0; l < 2; l++) {
            int fid = tid + l * 256;
            int kk = fid >> 5;
            int nq = (fid & 31) * 4;
            *(float4*)&Bs[kk][nq] = *(const float4*)&W[(k0 + kk) * 128 + nq];
        }
        __syncthreads();
#pragma unroll
        for (int k = 0; k < 16; k++) {
            float av[8], bv[8];
            *(float4*)&av[0] = *(float4*)&As[k][ty * 8];
            *(float4*)&av[4] = *(float4*)&As[k][ty * 8 + 4];
            *(float4*)&bv[0] = *(float4*)&Bs[k][tx * 8];
            *(float4*)&bv[4] = *(float4*)&Bs[k][tx * 8 + 4];
#pragma unroll
            for (int i = 0; i < 8; i++)
#pragma unroll
                for (int j = 0; j < 8; j++) acc[i][j] += av[i] * bv[j];
        }
        __syncthreads();
    }
#pragma unroll
    for (int i = 0; i < 8; i++) {
        int m = m0 + ty * 8 + i;
#pragma unroll
        for (int j = 0; j < 8; j += 4) {
            *(float4*)&g_h[m * 128 + tx * 8 + j] =
                make_float4(acc[i][j], acc[i][j + 1], acc[i][j + 2], acc[i][j + 3]);
        }
    }
}

// float <-> order-preserving uint32
__device__ __forceinline__ unsigned f2o(float x) {
    unsigned u = __float_as_uint(x);
    return u ^ ((u >> 31) ? 0xFFFFFFFFu : 0x80000000u);
}
__device__ __forceinline__ float o2f(unsigned u) {
    u ^= (u & 0x80000000u) ? 0x80000000u : 0xFFFFFFFFu;
    return __uint_as_float(u);
}

__device__ __forceinline__ float warp_incl_scan(float x, int lane) {
#pragma unroll
    for (int o = 1; o < 32; o <<= 1) {
        float y = __shfl_up_sync(0xffffffffu, x, o);
        if (lane >= o) x += y;
    }
    return x;
}

__device__ __forceinline__ float block_excl_pairsum(float ps, int lane, int wid,
                                                    float* wred) {
    float w = warp_incl_scan(ps, lane);
    if (lane == 31) wred[wid] = w;
    __syncthreads();
    if (wid == 0) {
        float s = wred[lane];
        s = warp_incl_scan(s, lane);
        wred[lane] = s;
    }
    __syncthreads();
    float base = (wid > 0) ? wred[wid - 1] : 0.f;
    return base + (w - ps);
}

// ---------------- Kernel 3 (side stream): hybrid bitonic sort + scans ----
__global__ __launch_bounds__(1024)
void sort_kernel() {
    __shared__ ull sk[2048];
    __shared__ float wred[32];
    __shared__ float sh_vmax;
    const int b = blockIdx.x, t = threadIdx.x;
    const int lane = t & 31, wid = t >> 5;

    ull e0 = ((ull)f2o(g_s2[b * 2048 + 2 * t]) << 32) | (unsigned)(2 * t);
    ull e1 = ((ull)f2o(g_s2[b * 2048 + 2 * t + 1]) << 32) | (unsigned)(2 * t + 1);

    for (int k = 2; k <= 2048; k <<= 1) {
        const bool asc = ((2 * t) & k) == 0;
        int j = k >> 1;
        for (; j >= 64; j >>= 1) {
            sk[2 * t] = e0; sk[2 * t + 1] = e1;
            __syncthreads();
            int m = j >> 1, p = t ^ m;
            ull f0 = sk[2 * p], f1 = sk[2 * p + 1];
            __syncthreads();
            bool keepmin = (((t & m) == 0) == asc);
            e0 = keepmin ? (e0 < f0 ? e0 : f0) : (e0 > f0 ? e0 : f0);
            e1 = keepmin ? (e1 < f1 ? e1 : f1) : (e1 > f1 ? e1 : f1);
        }
        for (; j >= 2; j >>= 1) {
            int m = j >> 1;
            ull f0 = __shfl_xor_sync(0xffffffffu, e0, m);
            ull f1 = __shfl_xor_sync(0xffffffffu, e1, m);
            bool keepmin = (((lane & m) == 0) == asc);
            e0 = keepmin ? (e0 < f0 ? e0 : f0) : (e0 > f0 ? e0 : f0);
            e1 = keepmin ? (e1 < f1 ? e1 : f1) : (e1 > f1 ? e1 : f1);
        }
        if ((e0 > e1) == asc) { ull tmp = e0; e0 = e1; e1 = tmp; }
    }

    float v0 = o2f((unsigned)(e0 >> 32));
    float v1 = o2f((unsigned)(e1 >> 32));
    g_v[b * 2048 + 2 * t]     = v0;
    g_v[b * 2048 + 2 * t + 1] = v1;
    g_perm[b * 2048 + 2 * t]     = (int)(unsigned)e0;
    g_perm[b * 2048 + 2 * t + 1] = (int)(unsigned)e1;
    if (t == 1023) sh_vmax = v1;
    __syncthreads();
    const float vmax = sh_vmax;

    float av0 = expf(ALPHA * v0), av1 = expf(ALPHA * v1);
    g_Ae[b * 2048 + 2 * t]     = av0;
    g_Ae[b * 2048 + 2 * t + 1] = av1;
    float exA = block_excl_pairsum(av0 + av1, lane, wid, wred);
    g_AS[b * 2049 + 2 * t + 1] = exA + av0;
    g_AS[b * 2049 + 2 * t + 2] = exA + av0 + av1;
    if (t == 0) g_AS[b * 2049] = 0.f;

    float ev0 = expf(v0 - vmax), ev1 = expf(v1 - vmax);
    g_Ee[b * 2048 + 2 * t]     = ev0;
    g_Ee[b * 2048 + 2 * t + 1] = ev1;
    float* sx = (float*)sk;
    __syncthreads();
    sx[2 * t] = ev0; sx[2 * t + 1] = ev1;
    __syncthreads();
    float r0 = sx[2047 - 2 * t];
    float r1 = sx[2046 - 2 * t];
    __syncthreads();
    float exE = block_excl_pairsum(r0 + r1, lane, wid, wred);
    g_ES[b * 2049 + 2047 - 2 * t] = exE + r0;
    g_ES[b * 2049 + 2046 - 2 * t] = exE + r0 + r1;
    if (t == 0) g_ES[b * 2049 + 2048] = 0.f;
}

// ---------------- Kernel 4: chunked vector scans (batched gathers) -------
__global__ __launch_bounds__(64)
void scanA_kernel() {
    const int b = blockIdx.x >> 7;
    const int c = blockIdx.x & 127;
    const int dir = threadIdx.x >> 5;
    const int lane = threadIdx.x & 31;
    const int kb = b * 2048 + c * CHK;
    const float4* h4 = (const float4*)g_h;

    int src[CHK]; float w[CHK];
    const float* wsrc = dir ? g_Ee : g_Ae;
#pragma unroll
    for (int r = 0; r < CHK; r++) {
        src[r] = __ldg(&g_perm[kb + r]);
        w[r]   = __ldg(&wsrc[kb + r]);
    }
    float4 hv[CHK];
#pragma unroll
    for (int r = 0; r < CHK; r++)
        hv[r] = __ldg(&h4[((b * 2048 + src[r]) << 5) + lane]);

    float4 run = make_float4(0.f, 0.f, 0.f, 0.f);
    if (dir == 0) {
        float4* o4 = (float4*)g_FWD;
#pragma unroll
        for (int r = 0; r < CHK; r++) {
            run.x += w[r] * hv[r].x; run.y += w[r] * hv[r].y;
            run.z += w[r] * hv[r].z; run.w += w[r] * hv[r].w;
            o4[((kb + r) << 5) + lane] = run;
        }
        ((float4*)g_TF)[((b * NCH + c) << 5) + lane] = run;
    } else {
        float4* o4 = (float4*)g_BWD;
#pragma unroll
        for (int r = CHK - 1; r >= 0; r--) {
            run.x += w[r] * hv[r].x; run.y += w[r] * hv[r].y;
            run.z += w[r] * hv[r].z; run.w += w[r] * hv[r].w;
            o4[((kb + r) << 5) + lane] = run;
        }
        ((float4*)g_TB)[((b * NCH + c) << 5) + lane] = run;
    }
}

// ---------------- Kernel 5: chunk totals -> exclusive offsets (parallel) -
__global__ __launch_bounds__(1024)
void scanB_kernel() {
    const int b = blockIdx.x >> 1;
    const int dir = blockIdx.x & 1;
    const int w = threadIdx.x >> 5;      // float4 channel 0..31
    const int lane = threadIdx.x & 31;   // chunk group 0..31 (4 chunks each)
    float4* T4 = dir ? (float4*)g_TB : (float4*)g_TF;

    float4 v[4]; int cc[4];
#pragma unroll
    for (int i = 0; i < 4; i++) {
        int o = lane * 4 + i;
        cc[i] = dir ? (NCH - 1 - o) : o;
        v[i] = T4[((b * NCH + cc[i]) << 5) + w];
    }
    float4 tot;
    tot.x = v[0].x + v[1].x + v[2].x + v[3].x;
    tot.y = v[0].y + v[1].y + v[2].y + v[3].y;
    tot.z = v[0].z + v[1].z + v[2].z + v[3].z;
    tot.w = v[0].w + v[1].w + v[2].w + v[3].w;
    float4 run;
    run.x = warp_incl_scan(tot.x, lane) - tot.x;
    run.y = warp_incl_scan(tot.y, lane) - tot.y;
    run.z = warp_incl_scan(tot.z, lane) - tot.z;
    run.w = warp_incl_scan(tot.w, lane) - tot.w;
#pragma unroll
    for (int i = 0; i < 4; i++) {
        T4[((b * NCH + cc[i]) << 5) + w] = run;
        run.x += v[i].x; run.y += v[i].y; run.z += v[i].z; run.w += v[i].w;
    }
}

// ---------------- Kernel 6: output -----------------------------------
__global__ __launch_bounds__(256)
void out_kernel(float* __restrict__ out) {
    __shared__ float sh_c1[8], sh_c2[8];
    __shared__ int   sh_k[8];
    const int lane = threadIdx.x & 31;
    const int rr = threadIdx.x >> 5;
    const int row = blockIdx.x * 8 + rr;
    const int b = row >> 11;

    if (lane == 0) {
        float s1 = __ldg(&g_s1[row]);
        const float* v = &g_v[b * 2048];
        float vmax = __ldg(&v[2047]);
        float T = -s1;
        int lo = 0, hi = 2048;
        while (lo < hi) {
            int mid = (lo + hi) >> 1;
            if (__ldg(&v[mid]) <= T) lo = mid + 1; else hi = mid;
        }
        int k = lo;
        float z = s1 + vmax;
        float m = z > 0.f ? z : ALPHA * z;
        float c1 = expf(z - m);
        float c2 = expf(ALPHA * s1 - m);
        float den = c1 * __ldg(&g_ES[b * 2049 + k]) + c2 * __ldg(&g_AS[b * 2049 + k]);
        float inv = 1.f / den;
        sh_k[rr] = k;
        sh_c1[rr] = c1 * inv;
        sh_c2[rr] = c2 * inv;
    }
    __syncthreads();

    const int k = sh_k[rr];
    const float c1 = sh_c1[rr], c2 = sh_c2[rr];
    float4 suf = make_float4(0.f, 0.f, 0.f, 0.f);
    float4 pre = make_float4(0.f, 0.f, 0.f, 0.f);
    if (k < 2048) {
        float4 s0 = __ldg(&((const float4*)g_BWD)[((b * 2048 + k) << 5) + lane]);
        float4 t0 = __ldg(&((const float4*)g_TB)[((b * NCH + (k >> 4)) << 5) + lane]);
        suf.x = s0.x + t0.x; suf.y = s0.y + t0.y;
        suf.z = s0.z + t0.z; suf.w = s0.w + t0.w;
    }
    if (k > 0) {
        float4 s0 = __ldg(&((const float4*)g_FWD)[((b * 2048 + k - 1) << 5) + lane]);
        float4 t0 = __ldg(&((const float4*)g_TF)[((b * NCH + ((k - 1) >> 4)) << 5) + lane]);
        pre.x = s0.x + t0.x; pre.y = s0.y + t0.y;
        pre.z = s0.z + t0.z; pre.w = s0.w + t0.w;
    }
    float4 hv = __ldg(&((const float4*)g_h)[(row << 5) + lane]);
    float4 o;
    o.x = c1 * suf.x + c2 * pre.x + ALPHA * hv.x;
    o.y = c1 * suf.y + c2 * pre.y + ALPHA * hv.y;
    o.z = c1 * suf.z + c2 * pre.z + ALPHA * hv.z;
    o.w = c1 * suf.w + c2 * pre.w + ALPHA * hv.w;
    o.x = o.x > 0.f ? o.x : (expf(o.x) - 1.f);
    o.y = o.y > 0.f ? o.y : (expf(o.y) - 1.f);
    o.z = o.z > 0.f ? o.z : (expf(o.z) - 1.f);
    o.w = o.w > 0.f ? o.w : (expf(o.w) - 1.f);
    ((float4*)out)[(row << 5) + lane] = o;
}

// ---------------- launcher: fork side stream for s12 + sort ----------
static cudaStream_t g_side = nullptr;
static cudaEvent_t g_ev_fork, g_ev_join;

extern "C" void kernel_launch(void* const* d_in, const int* in_sizes, int n_in,
                              void* d_out, int out_size) {
    const float* text = nullptr;
    const float* W = nullptr;
    const float* a = nullptr;
    for (int i = 0; i < n_in; i++) {
        if (in_sizes[i] == Bc * Nc * Cc)      text = (const float*)d_in[i];
        else if (in_sizes[i] == Cc * Cc)      W    = (const float*)d_in[i];
        else if (in_sizes[i] == 2 * Cc)       a    = (const float*)d_in[i];
    }
    float* out = (float*)d_out;

    if (!g_side) {
        cudaStreamCreateWithFlags(&g_side, cudaStreamNonBlocking);
        cudaEventCreateWithFlags(&g_ev_fork, cudaEventDisableTiming);
        cudaEventCreateWithFlags(&g_ev_join, cudaEventDisableTiming);
    }

    // fork: side stream computes w12 -> s1/s2 -> sort (independent of h)
    cudaEventRecord(g_ev_fork, 0);
    cudaStreamWaitEvent(g_side, g_ev_fork, 0);
    wvec_kernel<<<1, 128, 0, g_side>>>(W, a);
    s12_kernel<<<(Bc * Nc) / 8, 256, 0, g_side>>>(text);
    sort_kernel<<<Bc, 1024, 0, g_side>>>();
    cudaEventRecord(g_ev_join, g_side);

    // main stream: h = text @ W runs concurrently with the side chain
    gemm_kernel<<<(Bc * Nc) / 128, 256>>>(text, W);

    // join, then the dependent tail
    cudaStreamWaitEvent(0, g_ev_join, 0);
    scanA_kernel<<<Bc * NCH, 64>>>();
    scanB_kernel<<<Bc * 2, 1024>>>();
    out_kernel<<<(Bc * Nc) / 8, 256>>>(out);
}

// round 12
// speedup vs baseline: 2.0073x; 1.0260x over previous
#include <cuda_runtime.h>
#include <math.h>

#define ALPHA 0.2f
typedef unsigned long long ull;
constexpr int Bc = 8;
constexpr int Nc = 2048;
constexpr int Cc = 128;
constexpr int NCH = 128;           // chunks per batch
constexpr int CHK = 16;            // rows per chunk
constexpr int WSTRIDE = 132;       // smem W stride (conflict-free for LDS.64)
constexpr int GEMM_SMEM = 128 * WSTRIDE * 8;   // uint2 per element

// ---------------- device scratch ----------------
__device__ __align__(16) float g_h[Bc * Nc * Cc];
__device__ float g_s1[Bc * Nc];
__device__ float g_s2[Bc * Nc];
__device__ __align__(16) float g_w12[2 * Cc];
__device__ float g_v[Bc * Nc];
__device__ int   g_perm[Bc * Nc];
__device__ float g_Ae[Bc * Nc];
__device__ float g_Ee[Bc * Nc];
__device__ float g_AS[Bc * (Nc + 1)];
__device__ float g_ES[Bc * (Nc + 1)];
__device__ __align__(16) float g_FWD[Bc * Nc * Cc];
__device__ __align__(16) float g_BWD[Bc * Nc * Cc];
__device__ __align__(16) float g_TF[Bc * NCH * Cc];
__device__ __align__(16) float g_TB[Bc * NCH * Cc];

// ---------------- tf32 helpers ----------------
__device__ __forceinline__ unsigned f2tf(float x) {
    unsigned r; asm("cvt.rna.tf32.f32 %0, %1;" : "=r"(r) : "f"(x)); return r;
}

#define MMA_TF32(d, a, b) asm volatile( \
    "mma.sync.aligned.m16n8k8.row.col.f32.tf32.tf32.f32 " \
    "{%0,%1,%2,%3}, {%4,%5,%6,%7}, {%8,%9}, {%0,%1,%2,%3};" \
    : "+f"(d[0]), "+f"(d[1]), "+f"(d[2]), "+f"(d[3]) \
    : "r"(a[0]), "r"(a[1]), "r"(a[2]), "r"(a[3]), "r"(b[0]), "r"(b[1]))

// ---------------- Kernel 0 (side stream): w1 = W@a1, w2 = W@a2 -----------
__global__ __launch_bounds__(128)
void wvec_kernel(const float* __restrict__ W, const float* __restrict__ a) {
    const int c = threadIdx.x;
    const float4* Wr = (const float4*)&W[c * 128];
    float p1 = 0.f, p2 = 0.f;
#pragma unroll 8
    for (int q = 0; q < 32; q++) {
        float4 wv = __ldg(&Wr[q]);
        float4 a1 = __ldg(&((const float4*)a)[q]);
        float4 a2 = __ldg(&((const float4*)a)[32 + q]);
        p1 += wv.x * a1.x + wv.y * a1.y + wv.z * a1.z + wv.w * a1.w;
        p2 += wv.x * a2.x + wv.y * a2.y + wv.z * a2.z + wv.w * a2.w;
    }
    g_w12[c] = p1;
    g_w12[128 + c] = p2;
}

// ---------------- Kernel 0b (side stream): s1/s2 from text ---------------
__global__ __launch_bounds__(256)
void s12_kernel(const float* __restrict__ X) {
    int row = blockIdx.x * 8 + (threadIdx.x >> 5);
    int lane = threadIdx.x & 31;
    float4 hv = __ldg(&((const float4*)X)[(row << 5) + lane]);
    float4 a1 = ((const float4*)g_w12)[lane];
    float4 a2 = ((const float4*)g_w12)[32 + lane];
    float p1 = hv.x * a1.x + hv.y * a1.y + hv.z * a1.z + hv.w * a1.w;
    float p2 = hv.x * a2.x + hv.y * a2.y + hv.z * a2.z + hv.w * a2.w;
#pragma unroll
    for (int o = 16; o; o >>= 1) {
        p1 += __shfl_down_sync(0xffffffffu, p1, o);
        p2 += __shfl_down_sync(0xffffffffu, p2, o);
    }
    if (lane == 0) { g_s1[row] = p1; g_s2[row] = p2; }
}

// ---------------- Kernel 1 (main): h = text @ W via 3xTF32 tensor MMA ----
// grid 128, 256 thr; warp grid 4(M) x 2(N); warp tile 32x64.
__global__ __launch_bounds__(256)
void gemm_tc_kernel(const float* __restrict__ X, const float* __restrict__ Wg) {
    extern __shared__ uint2 Wd[];          // [n][k] padded, {hi, lo} tf32
    const int tid = threadIdx.x;

    // stage W: read [k][n] coalesced, write transposed [n][k] hi/lo
    for (int idx = tid; idx < 16384; idx += 256) {
        int k = idx >> 7, n = idx & 127;
        float w = __ldg(&Wg[idx]);
        unsigned hi = f2tf(w);
        float lo = w - __uint_as_float(hi);
        Wd[n * WSTRIDE + k] = make_uint2(hi, f2tf(lo));
    }
    __syncthreads();

    const int lane = tid & 31, warp = tid >> 5;
    const int mw = warp & 3, nw = warp >> 2;
    const int m_base = blockIdx.x * 128 + mw * 32;
    const int n_base = nw * 64;
    const int r = lane >> 2, c = lane & 3;

    float acc[2][8][4];
#pragma unroll
    for (int f = 0; f < 2; f++)
#pragma unroll
        for (int g = 0; g < 8; g++)
#pragma unroll
            for (int q = 0; q < 4; q++) acc[f][g][q] = 0.f;

    const float* Xb = X + (size_t)m_base * 128;
#pragma unroll 4
    for (int ks = 0; ks < 16; ks++) {
        const int k0 = ks * 8;
        unsigned ahi[2][4], alo[2][4];
#pragma unroll
        for (int f = 0; f < 2; f++) {
            const float* p = Xb + (f * 16 + r) * 128 + k0 + c;
            float a0 = __ldg(p);
            float a1 = __ldg(p + 8 * 128);
            float a2 = __ldg(p + 4);
            float a3 = __ldg(p + 8 * 128 + 4);
            ahi[f][0] = f2tf(a0); alo[f][0] = f2tf(a0 - __uint_as_float(ahi[f][0]));
            ahi[f][1] = f2tf(a1); alo[f][1] = f2tf(a1 - __uint_as_float(ahi[f][1]));
            ahi[f][2] = f2tf(a2); alo[f][2] = f2tf(a2 - __uint_as_float(ahi[f][2]));
            ahi[f][3] = f2tf(a3); alo[f][3] = f2tf(a3 - __uint_as_float(ahi[f][3]));
        }
        uint2 bA[8], bB[8];
#pragma unroll
        for (int g = 0; g < 8; g++) {
            int n = n_base + g * 8 + r;
            bA[g] = Wd[n * WSTRIDE + k0 + c];
            bB[g] = Wd[n * WSTRIDE + k0 + c + 4];
        }
#pragma unroll
        for (int f = 0; f < 2; f++)
#pragma unroll
            for (int g = 0; g < 8; g++) {
                unsigned bh[2] = { bA[g].x, bB[g].x };
                unsigned bl[2] = { bA[g].y, bB[g].y };
                MMA_TF32(acc[f][g], ahi[f], bh);
                MMA_TF32(acc[f][g], ahi[f], bl);
                MMA_TF32(acc[f][g], alo[f], bh);
            }
    }
    // epilogue: d0 (r, 2c), d1 (r, 2c+1), d2 (r+8, 2c), d3 (r+8, 2c+1)
#pragma unroll
    for (int f = 0; f < 2; f++)
#pragma unroll
        for (int g = 0; g < 8; g++) {
            int row = m_base + f * 16 + r;
            int col = n_base + g * 8 + 2 * c;
            *(float2*)&g_h[row * 128 + col] =
                make_float2(acc[f][g][0], acc[f][g][1]);
            *(float2*)&g_h[(row + 8) * 128 + col] =
                make_float2(acc[f][g][2], acc[f][g][3]);
        }
}

// float <-> order-preserving uint32
__device__ __forceinline__ unsigned f2o(float x) {
    unsigned u = __float_as_uint(x);
    return u ^ ((u >> 31) ? 0xFFFFFFFFu : 0x80000000u);
}
__device__ __forceinline__ float o2f(unsigned u) {
    u ^= (u & 0x80000000u) ? 0x80000000u : 0xFFFFFFFFu;
    return __uint_as_float(u);
}

__device__ __forceinline__ float warp_incl_scan(float x, int lane) {
#pragma unroll
    for (int o = 1; o < 32; o <<= 1) {
        float y = __shfl_up_sync(0xffffffffu, x, o);
        if (lane >= o) x += y;
    }
    return x;
}

__device__ __forceinline__ float block_excl_pairsum(float ps, int lane, int wid,
                                                    float* wred) {
    float w = warp_incl_scan(ps, lane);
    if (lane == 31) wred[wid] = w;
    __syncthreads();
    if (wid == 0) {
        float s = wred[lane];
        s = warp_incl_scan(s, lane);
        wred[lane] = s;
    }
    __syncthreads();
    float base = (wid > 0) ? wred[wid - 1] : 0.f;
    return base + (w - ps);
}

// ---------------- Kernel 3 (side stream): hybrid bitonic sort + scans ----
__global__ __launch_bounds__(1024)
void sort_kernel() {
    __shared__ ull sk[2048];
    __shared__ float wred[32];
    __shared__ float sh_vmax;
    const int b = blockIdx.x, t = threadIdx.x;
    const int lane = t & 31, wid = t >> 5;

    ull e0 = ((ull)f2o(g_s2[b * 2048 + 2 * t]) << 32) | (unsigned)(2 * t);
    ull e1 = ((ull)f2o(g_s2[b * 2048 + 2 * t + 1]) << 32) | (unsigned)(2 * t + 1);

    for (int k = 2; k <= 2048; k <<= 1) {
        const bool asc = ((2 * t) & k) == 0;
        int j = k >> 1;
        for (; j >= 64; j >>= 1) {
            sk[2 * t] = e0; sk[2 * t + 1] = e1;
            __syncthreads();
            int m = j >> 1, p = t ^ m;
            ull f0 = sk[2 * p], f1 = sk[2 * p + 1];
            __syncthreads();
            bool keepmin = (((t & m) == 0) == asc);
            e0 = keepmin ? (e0 < f0 ? e0 : f0) : (e0 > f0 ? e0 : f0);
            e1 = keepmin ? (e1 < f1 ? e1 : f1) : (e1 > f1 ? e1 : f1);
        }
        for (; j >= 2; j >>= 1) {
            int m = j >> 1;
            ull f0 = __shfl_xor_sync(0xffffffffu, e0, m);
            ull f1 = __shfl_xor_sync(0xffffffffu, e1, m);
            bool keepmin = (((lane & m) == 0) == asc);
            e0 = keepmin ? (e0 < f0 ? e0 : f0) : (e0 > f0 ? e0 : f0);
            e1 = keepmin ? (e1 < f1 ? e1 : f1) : (e1 > f1 ? e1 : f1);
        }
        if ((e0 > e1) == asc) { ull tmp = e0; e0 = e1; e1 = tmp; }
    }

    float v0 = o2f((unsigned)(e0 >> 32));
    float v1 = o2f((unsigned)(e1 >> 32));
    g_v[b * 2048 + 2 * t]     = v0;
    g_v[b * 2048 + 2 * t + 1] = v1;
    g_perm[b * 2048 + 2 * t]     = (int)(unsigned)e0;
    g_perm[b * 2048 + 2 * t + 1] = (int)(unsigned)e1;
    if (t == 1023) sh_vmax = v1;
    __syncthreads();
    const float vmax = sh_vmax;

    float av0 = expf(ALPHA * v0), av1 = expf(ALPHA * v1);
    g_Ae[b * 2048 + 2 * t]     = av0;
    g_Ae[b * 2048 + 2 * t + 1] = av1;
    float exA = block_excl_pairsum(av0 + av1, lane, wid, wred);
    g_AS[b * 2049 + 2 * t + 1] = exA + av0;
    g_AS[b * 2049 + 2 * t + 2] = exA + av0 + av1;
    if (t == 0) g_AS[b * 2049] = 0.f;

    float ev0 = expf(v0 - vmax), ev1 = expf(v1 - vmax);
    g_Ee[b * 2048 + 2 * t]     = ev0;
    g_Ee[b * 2048 + 2 * t + 1] = ev1;
    float* sx = (float*)sk;
    __syncthreads();
    sx[2 * t] = ev0; sx[2 * t + 1] = ev1;
    __syncthreads();
    float r0 = sx[2047 - 2 * t];
    float r1 = sx[2046 - 2 * t];
    __syncthreads();
    float exE = block_excl_pairsum(r0 + r1, lane, wid, wred);
    g_ES[b * 2049 + 2047 - 2 * t] = exE + r0;
    g_ES[b * 2049 + 2046 - 2 * t] = exE + r0 + r1;
    if (t == 0) g_ES[b * 2049 + 2048] = 0.f;
}

// ---------------- Kernel 4: chunked vector scans (batched gathers) -------
__global__ __launch_bounds__(64)
void scanA_kernel() {
    const int b = blockIdx.x >> 7;
    const int c = blockIdx.x & 127;
    const int dir = threadIdx.x >> 5;
    const int lane = threadIdx.x & 31;
    const int kb = b * 2048 + c * CHK;
    const float4* h4 = (const float4*)g_h;

    int src[CHK]; float w[CHK];
    const float* wsrc = dir ? g_Ee : g_Ae;
#pragma unroll
    for (int r = 0; r < CHK; r++) {
        src[r] = __ldg(&g_perm[kb + r]);
        w[r]   = __ldg(&wsrc[kb + r]);
    }
    float4 hv[CHK];
#pragma unroll
    for (int r = 0; r < CHK; r++)
        hv[r] = __ldg(&h4[((b * 2048 + src[r]) << 5) + lane]);

    float4 run = make_float4(0.f, 0.f, 0.f, 0.f);
    if (dir == 0) {
        float4* o4 = (float4*)g_FWD;
#pragma unroll
        for (int r = 0; r < CHK; r++) {
            run.x += w[r] * hv[r].x; run.y += w[r] * hv[r].y;
            run.z += w[r] * hv[r].z; run.w += w[r] * hv[r].w;
            o4[((kb + r) << 5) + lane] = run;
        }
        ((float4*)g_TF)[((b * NCH + c) << 5) + lane] = run;
    } else {
        float4* o4 = (float4*)g_BWD;
#pragma unroll
        for (int r = CHK - 1; r >= 0; r--) {
            run.x += w[r] * hv[r].x; run.y += w[r] * hv[r].y;
            run.z += w[r] * hv[r].z; run.w += w[r] * hv[r].w;
            o4[((kb + r) << 5) + lane] = run;
        }
        ((float4*)g_TB)[((b * NCH + c) << 5) + lane] = run;
    }
}

// ---------------- Kernel 5: chunk totals -> exclusive offsets (parallel) -
__global__ __launch_bounds__(1024)
void scanB_kernel() {
    const int b = blockIdx.x >> 1;
    const int dir = blockIdx.x & 1;
    const int w = threadIdx.x >> 5;
    const int lane = threadIdx.x & 31;
    float4* T4 = dir ? (float4*)g_TB : (float4*)g_TF;

    float4 v[4]; int cc[4];
#pragma unroll
    for (int i = 0; i < 4; i++) {
        int o = lane * 4 + i;
        cc[i] = dir ? (NCH - 1 - o) : o;
        v[i] = T4[((b * NCH + cc[i]) << 5) + w];
    }
    float4 tot;
    tot.x = v[0].x + v[1].x + v[2].x + v[3].x;
    tot.y = v[0].y + v[1].y + v[2].y + v[3].y;
    tot.z = v[0].z + v[1].z + v[2].z + v[3].z;
    tot.w = v[0].w + v[1].w + v[2].w + v[3].w;
    float4 run;
    run.x = warp_incl_scan(tot.x, lane) - tot.x;
    run.y = warp_incl_scan(tot.y, lane) - tot.y;
    run.z = warp_incl_scan(tot.z, lane) - tot.z;
    run.w = warp_incl_scan(tot.w, lane) - tot.w;
#pragma unroll
    for (int i = 0; i < 4; i++) {
        T4[((b * NCH + cc[i]) << 5) + w] = run;
        run.x += v[i].x; run.y += v[i].y; run.z += v[i].z; run.w += v[i].w;
    }
}

// ---------------- Kernel 6: output -----------------------------------
__global__ __launch_bounds__(256)
void out_kernel(float* __restrict__ out) {
    __shared__ float sh_c1[8], sh_c2[8];
    __shared__ int   sh_k[8];
    const int lane = threadIdx.x & 31;
    const int rr = threadIdx.x >> 5;
    const int row = blockIdx.x * 8 + rr;
    const int b = row >> 11;

    if (lane == 0) {
        float s1 = __ldg(&g_s1[row]);
        const float* v = &g_v[b * 2048];
        float vmax = __ldg(&v[2047]);
        float T = -s1;
        int lo = 0, hi = 2048;
        while (lo < hi) {
            int mid = (lo + hi) >> 1;
            if (__ldg(&v[mid]) <= T) lo = mid + 1; else hi = mid;
        }
        int k = lo;
        float z = s1 + vmax;
        float m = z > 0.f ? z : ALPHA * z;
        float c1 = expf(z - m);
        float c2 = expf(ALPHA * s1 - m);
        float den = c1 * __ldg(&g_ES[b * 2049 + k]) + c2 * __ldg(&g_AS[b * 2049 + k]);
        float inv = 1.f / den;
        sh_k[rr] = k;
        sh_c1[rr] = c1 * inv;
        sh_c2[rr] = c2 * inv;
    }
    __syncthreads();

    const int k = sh_k[rr];
    const float c1 = sh_c1[rr], c2 = sh_c2[rr];
    float4 suf = make_float4(0.f, 0.f, 0.f, 0.f);
    float4 pre = make_float4(0.f, 0.f, 0.f, 0.f);
    if (k < 2048) {
        float4 s0 = __ldg(&((const float4*)g_BWD)[((b * 2048 + k) << 5) + lane]);
        float4 t0 = __ldg(&((const float4*)g_TB)[((b * NCH + (k >> 4)) << 5) + lane]);
        suf.x = s0.x + t0.x; suf.y = s0.y + t0.y;
        suf.z = s0.z + t0.z; suf.w = s0.w + t0.w;
    }
    if (k > 0) {
        float4 s0 = __ldg(&((const float4*)g_FWD)[((b * 2048 + k - 1) << 5) + lane]);
        float4 t0 = __ldg(&((const float4*)g_TF)[((b * NCH + ((k - 1) >> 4)) << 5) + lane]);
        pre.x = s0.x + t0.x; pre.y = s0.y + t0.y;
        pre.z = s0.z + t0.z; pre.w = s0.w + t0.w;
    }
    float4 hv = __ldg(&((const float4*)g_h)[(row << 5) + lane]);
    float4 o;
    o.x = c1 * suf.x + c2 * pre.x + ALPHA * hv.x;
    o.y = c1 * suf.y + c2 * pre.y + ALPHA * hv.y;
    o.z = c1 * suf.z + c2 * pre.z + ALPHA * hv.z;
    o.w = c1 * suf.w + c2 * pre.w + ALPHA * hv.w;
    o.x = o.x > 0.f ? o.x : (expf(o.x) - 1.f);
    o.y = o.y > 0.f ? o.y : (expf(o.y) - 1.f);
    o.z = o.z > 0.f ? o.z : (expf(o.z) - 1.f);
    o.w = o.w > 0.f ? o.w : (expf(o.w) - 1.f);
    ((float4*)out)[(row << 5) + lane] = o;
}

// ---------------- launcher ----------------
static cudaStream_t g_side = nullptr;
static cudaEvent_t g_ev_fork, g_ev_join;

extern "C" void kernel_launch(void* const* d_in, const int* in_sizes, int n_in,
                              void* d_out, int out_size) {
    const float* text = nullptr;
    const float* W = nullptr;
    const float* a = nullptr;
    for (int i = 0; i < n_in; i++) {
        if (in_sizes[i] == Bc * Nc * Cc)      text = (const float*)d_in[i];
        else if (in_sizes[i] == Cc * Cc)      W    = (const float*)d_in[i];
        else if (in_sizes[i] == 2 * Cc)       a    = (const float*)d_in[i];
    }
    float* out = (float*)d_out;

    if (!g_side) {
        cudaStreamCreateWithFlags(&g_side, cudaStreamNonBlocking);
        cudaEventCreateWithFlags(&g_ev_fork, cudaEventDisableTiming);
        cudaEventCreateWithFlags(&g_ev_join, cudaEventDisableTiming);
        cudaFuncSetAttribute(gemm_tc_kernel,
                             cudaFuncAttributeMaxDynamicSharedMemorySize,
                             GEMM_SMEM);
    }

    // fork: side stream computes w12 -> s1/s2 -> sort (independent of h)
    cudaEventRecord(g_ev_fork, 0);
    cudaStreamWaitEvent(g_side, g_ev_fork, 0);
    wvec_kernel<<<1, 128, 0, g_side>>>(W, a);
    s12_kernel<<<(Bc * Nc) / 8, 256, 0, g_side>>>(text);
    sort_kernel<<<Bc, 1024, 0, g_side>>>();
    cudaEventRecord(g_ev_join, g_side);

    // main stream: tensor-core h = text @ W runs concurrently
    gemm_tc_kernel<<<(Bc * Nc) / 128, 256, GEMM_SMEM>>>(text, W);

    // join, then the dependent tail
    cudaStreamWaitEvent(0, g_ev_join, 0);
    scanA_kernel<<<Bc * NCH, 64>>>();
    scanB_kernel<<<Bc * 2, 1024>>>();
    out_kernel<<<(Bc * Nc) / 8, 256>>>(out);
}